// round 17
// baseline (speedup 1.0000x reference)
#include <cuda_runtime.h>
#include <math_constants.h>
#include <cstdint>

#define D_MODEL  1024
#define ALPHA    0.5f
#define WINDOW   64          // 0.5^64 ~ 5e-20: truncation far below 1e-3 rel-err
#define CHUNK    1024        // tokens per consumer block
#define ROWS_PER_BLOCK 8     // producer: 8 warps/block, 1 row each

#define MAX_TOKENS 262144
#define MAX_CHUNKS (MAX_TOKENS / CHUNK)     // 256

// Tagged slots: low 32 bits = score, high 32 bits = epoch tag. A single 8-byte
// relaxed store publishes value+readiness atomically -> NO producer fences.
// g_epoch: completed-launch count. Producers/consumers tag with g_epoch+1; the
// final consumer bumps g_epoch (after all consumers have read it), making the
// protocol self-consistent across graph replays. Stale tags from launch L are
// L+1 != L+2 expected by launch L+1, so stale data is never consumed.
__device__ unsigned long long g_slots[MAX_TOKENS];
__device__ unsigned g_epoch;
__device__ unsigned g_done;

__device__ __forceinline__ void atomic_max_float(float* addr, float val)
{
    // Global max is known-positive (~2.9); 0xAA poison is a tiny negative
    // float whose signed-int rep loses to any positive posting.
    if (val >= 0.f)
        atomicMax(reinterpret_cast<int*>(addr), __float_as_int(val));
    else
        atomicMin(reinterpret_cast<unsigned int*>(addr), __float_as_uint(val));
}

// ---------------------------------------------------------------------------
// Single kernel, two block roles.
//   bid < nprod : PRODUCER — frozen R9 score body (7.45 TB/s). Only deltas:
//                 one __ldg of g_epoch at entry; the final store is an 8-byte
//                 relaxed {score,tag} instead of a 4-byte STG. No fences —
//                 fences here cost 12-127 us (R10/R12 evidence).
//   bid >= nprod: CONSUMER — 256 trailing blocks (dispatched last). Stage
//                 chunk + 64-halo into smem by polling slot tags (relaxed,
//                 L1-bypassing loads), then windowed EMA + block max +
//                 atomicMax. Last consumer bumps the epoch.
// Deadlock-free: <=256 spinners vs >=1100 resident CTA slots; producers never
// wait, so they always make progress regardless of dispatch interleaving.
// ---------------------------------------------------------------------------
__global__ __launch_bounds__(256)
void ema_probe_kernel(const float* __restrict__ x,
                      const float* __restrict__ W,
                      const float* __restrict__ b,
                      float* __restrict__ out,
                      int n, int nprod)
{
    const int tid  = threadIdx.x;
    const int warp = tid >> 5;
    const int lane = tid & 31;
    const int bid  = blockIdx.x;

    // Tag for this launch. Safe via __ldg: g_epoch is only written by the last
    // consumer, strictly after every producer/consumer has already read it.
    const unsigned E1 = __ldg(&g_epoch) + 1u;

    if (bid < nprod) {
        // ================= PRODUCER (frozen R9 body) =================
        if (bid == 0 && tid == 0)
            *out = -CUDART_INF_F;     // overwrite 0xAA poison (wave 1; consumers run last)

        const int row = bid * ROWS_PER_BLOCK + warp;
        if (row < n) {
            float4 w[8];
            const float4* W4 = reinterpret_cast<const float4*>(W);
            #pragma unroll
            for (int i = 0; i < 8; i++)
                w[i] = __ldg(&W4[lane + i * 32]);

            const float4* xr =
                reinterpret_cast<const float4*>(x + (size_t)row * D_MODEL);

            float4 xv[8];
            #pragma unroll
            for (int i = 0; i < 8; i++)              // 8 front-batched LDG.128
                xv[i] = __ldcs(&xr[lane + i * 32]);

            float acc = 0.f;
            #pragma unroll
            for (int i = 0; i < 8; i++) {
                acc = fmaf(xv[i].x, w[i].x, acc);
                acc = fmaf(xv[i].y, w[i].y, acc);
                acc = fmaf(xv[i].z, w[i].z, acc);
                acc = fmaf(xv[i].w, w[i].w, acc);
            }
            #pragma unroll
            for (int o = 16; o; o >>= 1)
                acc += __shfl_xor_sync(0xffffffffu, acc, o);

            if (lane == 0) {
                const float sc = acc + __ldg(b);
                const unsigned long long payload =
                    (unsigned long long)__float_as_uint(sc) |
                    ((unsigned long long)E1 << 32);
                // Single 8B relaxed store: value + readiness, no MEMBAR.
                asm volatile("st.relaxed.gpu.global.u64 [%0], %1;"
                             :: "l"(&g_slots[row]), "l"(payload) : "memory");
            }
        }
        return;
    }

    // ================= CONSUMER =================
    const int nchunk = (n + CHUNK - 1) / CHUNK;
    const int e      = bid - nprod;
    if (e >= nchunk) return;
    const int base = e * CHUNK;

    __shared__ float s[CHUNK + WINDOW];
    __shared__ float wmax[8];

    // Stage halo + chunk, polling each slot's tag. Relaxed loads bypass L1
    // (point of coherence = L2), so retries always observe fresh data.
    for (int i = tid; i < CHUNK + WINDOW; i += 256) {
        const int g = base - WINDOW + i;
        float val = 0.f;                              // pre-sequence / OOB -> 0
        if (g >= 0 && g < n) {
            unsigned long long p;
            while (true) {
                asm volatile("ld.relaxed.gpu.global.u64 %0, [%1];"
                             : "=l"(p) : "l"(&g_slots[g]));
                if ((unsigned)(p >> 32) == E1) break;
                __nanosleep(128);
            }
            val = __uint_as_float((unsigned)p);
        }
        s[i] = val;
    }
    __syncthreads();

    // Windowed EMA: thread handles 4 consecutive tokens starting at p.
    // Seed via 4 independent 16-FMA chains (exact: group weight 0.5^16).
    const int p = tid * 4;
    float a0 = 0.f, a1 = 0.f, a2 = 0.f, a3 = 0.f, wc = ALPHA;
    #pragma unroll
    for (int k = 0; k < 16; k++) {
        a0 = fmaf(wc, s[WINDOW + p - k],      a0);
        a1 = fmaf(wc, s[WINDOW + p - 16 - k], a1);
        a2 = fmaf(wc, s[WINDOW + p - 32 - k], a2);
        a3 = fmaf(wc, s[WINDOW + p - 48 - k], a3);
        wc *= (1.0f - ALPHA);
    }
    const float c16 = 1.0f / 65536.0f;               // 0.5^16
    float eacc = fmaf(c16, fmaf(c16, fmaf(c16, a3, a2), a1), a0);
    float m = (base + p < n) ? eacc : -CUDART_INF_F;

    #pragma unroll
    for (int j = 1; j < 4; j++) {                    // exact recurrence
        eacc = fmaf(ALPHA, s[WINDOW + p + j], (1.0f - ALPHA) * eacc);
        if (base + p + j < n) m = fmaxf(m, eacc);
    }

    // Block max + one global atomic per block
    #pragma unroll
    for (int o = 16; o; o >>= 1)
        m = fmaxf(m, __shfl_xor_sync(0xffffffffu, m, o));
    if (lane == 0) wmax[warp] = m;
    __syncthreads();
    if (tid < 8) {
        float r = wmax[tid];
        #pragma unroll
        for (int o = 4; o; o >>= 1)
            r = fmaxf(r, __shfl_xor_sync(0xffu, r, o));
        if (tid == 0)
            atomic_max_float(out, r);
    }

    // Epoch bookkeeping: the LAST consumer (all others have necessarily read
    // g_epoch already) resets the done-counter and advances the epoch for the
    // next launch / graph replay.
    __syncthreads();
    if (tid == 0) {
        const unsigned d = atomicAdd(&g_done, 1u) + 1u;
        if (d == (unsigned)nchunk) {
            atomicExch(&g_done, 0u);
            atomicAdd(&g_epoch, 1u);
        }
    }
}

// ---------------------------------------------------------------------------
extern "C" void kernel_launch(void* const* d_in, const int* in_sizes, int n_in,
                              void* d_out, int out_size)
{
    const float* x = (const float*)d_in[0];
    const float* W = (const float*)d_in[1];
    const float* b = (const float*)d_in[2];
    float* out     = (float*)d_out;

    const int n = in_sizes[0] / D_MODEL;                           // 262144
    const int nprod  = (n + ROWS_PER_BLOCK - 1) / ROWS_PER_BLOCK;  // 32768
    const int nchunk = (n + CHUNK - 1) / CHUNK;                    // 256

    ema_probe_kernel<<<nprod + nchunk, 256>>>(x, W, b, out, n, nprod);
}